// round 10
// baseline (speedup 1.0000x reference)
#include <cuda_runtime.h>
#include <cuda_bf16.h>
#include <math.h>
#include <stdint.h>

#define B_    8
#define L_    2048
#define D_    256
#define N_    16
#define R_    16
#define NPROJ 80
#define CL    32          // scan chunk length
#define NC    (L_/CL)     // 64 chunks
#define SEGC  (NC/4)      // 16 chunks per combine segment

typedef unsigned long long ull;

// ---------------- scratch (device globals) ----------------
__device__ float    g_delta  [B_*L_*D_];
__device__ float    g_delta_b[B_*L_*D_];
__device__ float    g_BC     [B_*L_*48];      // Bf(16) Bb(16) C(16)
__device__ float    g_pc     [B_*L_*D_];      // cumulative p1 within chunk
__device__ float    g_P      [B_*NC*N_*D_];
__device__ float    g_H      [B_*NC*N_*D_];
__device__ float    g_hs     [B_*NC*N_*D_];
__device__ float    g_y      [B_*L_*D_];      // y_local (pre-correction)
__device__ uint32_t g_y16    [B_*L_*D_];      // final y packed (bf16 hi | lo<<16)
__device__ uint32_t g_W16    [D_*D_];         // W_out packed (bf16 hi | lo<<16)

__device__ __forceinline__ float softplusf(float v) {
    return v > 20.0f ? v : log1pf(__expf(v));
}

__device__ __forceinline__ uint32_t pack_hilo(float v) {
    __nv_bfloat16 h = __float2bfloat16(v);
    __nv_bfloat16 l = __float2bfloat16(v - __bfloat162float(h));
    return (uint32_t)__bfloat16_as_ushort(h) |
           ((uint32_t)__bfloat16_as_ushort(l) << 16);
}

// ---------------- packed f32x2 helpers ----------------
__device__ __forceinline__ ull pack2(float lo, float hi) {
    ull r;
    asm("mov.b64 %0, {%1, %2};" : "=l"(r) : "f"(lo), "f"(hi));
    return r;
}
__device__ __forceinline__ void unpack2(ull v, float& lo, float& hi) {
    asm("mov.b64 {%0, %1}, %2;" : "=f"(lo), "=f"(hi) : "l"(v));
}
__device__ __forceinline__ ull mul2(ull a, ull b) {
    ull d;
    asm("mul.rn.f32x2 %0, %1, %2;" : "=l"(d) : "l"(a), "l"(b));
    return d;
}
__device__ __forceinline__ ull fma2(ull a, ull b, ull c) {
    ull d;
    asm("fma.rn.f32x2 %0, %1, %2, %3;" : "=l"(d) : "l"(a), "l"(b), "l"(c));
    return d;
}
// e2[k] = (p^(2k+1), p^(2k+2)), k=0..7 (array form, used outside hot loops)
__device__ __forceinline__ void powers16_p2(float p1, ull e2[8]) {
    const float p1sq = p1 * p1;
    e2[0] = pack2(p1, p1sq);
    const ull pstep = pack2(p1sq, p1sq);
    #pragma unroll
    for (int k = 1; k < 8; ++k) e2[k] = mul2(e2[k-1], pstep);
}

__device__ __forceinline__ float check_A(const float* __restrict__ A_log,
                                         int d, bool& fast) {
    float a0 = -__expf(__ldg(A_log + d*N_));
    fast = true;
    #pragma unroll
    for (int n = 1; n < N_; ++n) {
        float an = -__expf(__ldg(A_log + d*N_ + n));
        fast = fast && (fabsf(an - a0*(float)(n+1)) <= 1e-4f*(float)(n+1));
    }
    return a0;
}

// ---------------------------------------------------------------------------
// Kernel 0: pack W_out to bf16 hi/lo once.
// ---------------------------------------------------------------------------
__global__ __launch_bounds__(256) void packW_kernel(const float* __restrict__ Wout)
{
    const int i = blockIdx.x*256 + threadIdx.x;
    g_W16[i] = pack_hilo(Wout[i]);
}

// ---------------------------------------------------------------------------
// Kernel 1: fused projections (unchanged).
// ---------------------------------------------------------------------------
__global__ __launch_bounds__(256) void proj_kernel(
    const float* __restrict__ x, const float* __restrict__ Wxp,
    const float* __restrict__ Wxb, const float* __restrict__ Wdt,
    const float* __restrict__ bdt)
{
    const int ROWS = 16;
    __shared__ float sx[ROWS][D_];
    __shared__ float sp[ROWS][NPROJ];
    __shared__ float sWdtT[R_][D_];

    const int row0 = blockIdx.x * ROWS;
    const int tid  = threadIdx.x;

    for (int i = tid; i < D_*R_; i += 256) {
        int d = i / R_, r = i % R_;
        sWdtT[r][d] = Wdt[i];
    }
    for (int i = tid; i < ROWS*D_; i += 256)
        sx[i >> 8][i & 255] = x[row0*D_ + i];
    __syncthreads();

    const int warp = tid >> 5, lane = tid & 31;
    #pragma unroll
    for (int t = 0; t < 10; ++t) {
        int j = warp + 8*t;
        const float* Wrow = (j < 64) ? (Wxp + j*D_) : (Wxb + (j-64)*D_);
        float wv[8];
        #pragma unroll
        for (int k = 0; k < 8; ++k) wv[k] = __ldg(Wrow + lane + 32*k);
        for (int r = 0; r < ROWS; ++r) {
            float acc = 0.f;
            #pragma unroll
            for (int k = 0; k < 8; ++k) acc = fmaf(wv[k], sx[r][lane + 32*k], acc);
            #pragma unroll
            for (int o = 16; o; o >>= 1) acc += __shfl_xor_sync(0xffffffffu, acc, o);
            if (lane == 0) sp[r][j] = acc;
        }
    }
    __syncthreads();

    for (int i = tid; i < ROWS*48; i += 256) {
        int r = i / 48, c = i - r*48;
        g_BC[(row0 + r)*48 + c] = sp[r][16 + c];
    }

    float wdt[R_];
    #pragma unroll
    for (int q = 0; q < R_; ++q) wdt[q] = sWdtT[q][tid];
    const float bv = bdt[tid];

    for (int r = 0; r < ROWS; ++r) {
        float s = bv, sb = bv;
        #pragma unroll
        for (int q = 0; q < R_; ++q) {
            s  = fmaf(sp[r][q],      wdt[q], s);
            sb = fmaf(sp[r][64 + q], wdt[q], sb);
        }
        const int m = row0 + r;
        const int b = m >> 11;
        const int l = m & (L_ - 1);
        g_delta[m*D_ + tid]                              = softplusf(s);
        g_delta_b[((b << 11) + (L_ - 1 - l))*D_ + tid]   = softplusf(sb);
    }
}

// ---------------------------------------------------------------------------
// Kernel 2: scan_local — packed f32x2, reg-dieted to 4 CTAs/SM (single wave).
// ---------------------------------------------------------------------------
__global__ __launch_bounds__(256, 4) void scan_local_kernel(
    const float* __restrict__ x, const float* __restrict__ A_log,
    const float* __restrict__ Dskip)
{
    const int bc = blockIdx.x;
    const int b = bc / NC, c = bc - b*NC;
    const int d = threadIdx.x;
    const int l0 = c * CL;

    __shared__ __align__(16) float sB[CL][48];
    for (int i = d; i < CL*48; i += 256) {
        int t = i / 48, j = i - t*48;
        sB[t][j] = g_BC[(b*L_ + l0 + t)*48 + j];
    }
    __syncthreads();

    bool fast;
    const float a0 = check_A(A_log, d, fast);
    const float dsk = Dskip[d];

    const float* dl_ptr  = g_delta   + (b*L_ + l0)*D_ + d;
    const float* dlb_ptr = g_delta_b + (b*L_ + l0)*D_ + d;
    const float* x_ptr   = x + (b*L_ + l0)*D_ + d;
    const float* xr_ptr  = x + (b*L_ + (L_ - 1 - l0))*D_ + d;
    float* y_ptr  = g_y  + (b*L_ + l0)*D_ + d;
    float* pc_ptr = g_pc + (b*L_ + l0)*D_ + d;

    float* Pp = g_P + ((b*NC + c)*N_)*D_ + d;
    float* Hp = g_H + ((b*NC + c)*N_)*D_ + d;

    if (fast) {
        ull h2[8];
        #pragma unroll
        for (int k = 0; k < 8; ++k) h2[k] = 0ull;
        float p1 = 1.f;

        #pragma unroll
        for (int t0 = 0; t0 < CL; t0 += 4) {
            float dl[4], dlb[4], xv[4], xr[4];
            #pragma unroll
            for (int i = 0; i < 4; ++i) {
                dl[i]  = dl_ptr [(t0+i)*D_];
                dlb[i] = dlb_ptr[(t0+i)*D_];
                xv[i]  = x_ptr  [(t0+i)*D_];
                xr[i]  = xr_ptr [-(t0+i)*D_];
            }
            #pragma unroll
            for (int i = 0; i < 4; ++i) {
                const int t = t0 + i;
                const float e1 = __expf(dl[i] * a0);
                const float e1sq = e1 * e1;
                ull e = pack2(e1, e1sq);               // running power pair
                const ull estep = pack2(e1sq, e1sq);
                const float c1 = dl[i]*xv[i], c2 = dlb[i]*xr[i];
                const ull c1p = pack2(c1, c1);
                const ull c2p = pack2(c2, c2);
                ull y2 = 0ull;
                const ull* Bf2 = reinterpret_cast<const ull*>(&sB[t][0]);
                const ull* Bb2 = reinterpret_cast<const ull*>(&sB[t][16]);
                const ull* C2  = reinterpret_cast<const ull*>(&sB[t][32]);
                #pragma unroll
                for (int k = 0; k < 8; ++k) {
                    const ull du = fma2(c1p, Bf2[k], mul2(c2p, Bb2[k]));
                    h2[k] = fma2(e, h2[k], du);
                    y2    = fma2(h2[k], C2[k], y2);
                    if (k < 7) e = mul2(e, estep);
                }
                p1 *= e1;
                float ylo, yhi; unpack2(y2, ylo, yhi);
                y_ptr [t*D_] = fmaf(xv[i] + xr[i], dsk, ylo + yhi);
                pc_ptr[t*D_] = p1;
            }
        }
        ull pw2[8]; powers16_p2(p1, pw2);
        #pragma unroll
        for (int k = 0; k < 8; ++k) {
            float plo, phi; unpack2(pw2[k], plo, phi);
            float hlo, hhi; unpack2(h2[k], hlo, hhi);
            Pp[(2*k  )*D_] = plo;  Pp[(2*k+1)*D_] = phi;
            Hp[(2*k  )*D_] = hlo;  Hp[(2*k+1)*D_] = hhi;
        }
    } else {
        float h[N_], a[N_], p[N_];
        #pragma unroll
        for (int n = 0; n < N_; ++n) {
            a[n] = -__expf(__ldg(A_log + d*N_ + n));
            p[n] = 1.f;
            h[n] = 0.f;
        }
        for (int t = 0; t < CL; ++t) {
            const float dl  = dl_ptr[t*D_];
            const float dlb = dlb_ptr[t*D_];
            const float xv  = x_ptr[t*D_];
            const float xr  = xr_ptr[-t*D_];
            const float c1 = dl*xv, c2 = dlb*xr;
            float y = 0.f;
            #pragma unroll
            for (int n = 0; n < N_; ++n) {
                const float e = __expf(dl * a[n]);
                h[n] = fmaf(e, h[n], fmaf(c1, sB[t][n], c2 * sB[t][16+n]));
                y    = fmaf(h[n], sB[t][32+n], y);
                p[n] *= e;
            }
            y_ptr[t*D_] = fmaf(xv + xr, dsk, y);
        }
        #pragma unroll
        for (int n = 0; n < N_; ++n) { Pp[n*D_] = p[n]; Hp[n*D_] = h[n]; }
    }
}

// ---------------------------------------------------------------------------
// Kernel 3: combine — segmented affine scan (unchanged).
// ---------------------------------------------------------------------------
__global__ __launch_bounds__(512) void combine_kernel()
{
    const int bn = blockIdx.x;          // 0..127
    const int b = bn >> 4;
    const int n = bn & 15;
    const int seg = threadIdx.x >> 7;   // 0..3
    const int dp  = threadIdx.x & 127;  // d-pair

    __shared__ ull sP[4][128];
    __shared__ ull sH[4][128];

    const ull* P2 = reinterpret_cast<const ull*>(g_P);
    const ull* H2 = reinterpret_cast<const ull*>(g_H);
    ull* hs2 = reinterpret_cast<ull*>(g_hs);

    const int c0 = seg * SEGC;
    #define CIDX(c) ((((b*NC + (c))*N_) + n)*128 + dp)

    ull Pc = pack2(1.f, 1.f), Hc = 0ull;
    #pragma unroll 4
    for (int i = 0; i < SEGC; ++i) {
        const int idx = CIDX(c0 + i);
        const ull p = P2[idx];
        Pc = mul2(p, Pc);
        Hc = fma2(p, Hc, H2[idx]);
    }
    sP[seg][dp] = Pc;
    sH[seg][dp] = Hc;
    __syncthreads();

    ull h = 0ull;
    #pragma unroll
    for (int t = 0; t < 3; ++t)
        if (t < seg) h = fma2(sP[t][dp], h, sH[t][dp]);

    #pragma unroll 4
    for (int i = 0; i < SEGC; ++i) {
        const int idx = CIDX(c0 + i);
        hs2[idx] = h;
        h = fma2(P2[idx], h, H2[idx]);
    }
    #undef CIDX
}

// ---------------------------------------------------------------------------
// Kernel 4: correct2 — emits final y packed; pw via running chain.
// ---------------------------------------------------------------------------
__global__ __launch_bounds__(256) void correct2_kernel(
    const float* __restrict__ A_log)
{
    const int bc = blockIdx.x;
    const int b = bc / NC, c = bc - b*NC;
    const int d = threadIdx.x;
    const int l0 = c * CL;

    __shared__ __align__(16) float sC[CL][N_];
    for (int i = d; i < CL*N_; i += 256) {
        int t = i >> 4, j = i & 15;
        sC[t][j] = g_BC[(b*L_ + l0 + t)*48 + 32 + j];
    }
    __syncthreads();

    bool fast;
    const float a0 = check_A(A_log, d, fast);
    (void)a0;

    const float* y_ptr  = g_y  + (b*L_ + l0)*D_ + d;
    uint32_t* y16_ptr   = g_y16 + (b*L_ + l0)*D_ + d;
    const float* pc_ptr = g_pc + (b*L_ + l0)*D_ + d;

    if (fast) {
        ull q2[8];
        #pragma unroll
        for (int k = 0; k < 8; ++k) {
            const float qlo = g_hs[((b*NC + c)*N_ + 2*k  )*D_ + d];
            const float qhi = g_hs[((b*NC + c)*N_ + 2*k+1)*D_ + d];
            q2[k] = pack2(qlo, qhi);
        }
        #pragma unroll
        for (int t0 = 0; t0 < CL; t0 += 4) {
            float p1[4], yl[4];
            #pragma unroll
            for (int i = 0; i < 4; ++i) {
                p1[i] = pc_ptr[(t0+i)*D_];
                yl[i] = y_ptr [(t0+i)*D_];
            }
            #pragma unroll
            for (int i = 0; i < 4; ++i) {
                const int t = t0 + i;
                const float psq = p1[i] * p1[i];
                ull pw = pack2(p1[i], psq);            // running power pair
                const ull pstep = pack2(psq, psq);
                const ull* C2 = reinterpret_cast<const ull*>(&sC[t][0]);
                ull corr2 = 0ull;
                #pragma unroll
                for (int k = 0; k < 8; ++k) {
                    corr2 = fma2(mul2(pw, q2[k]), C2[k], corr2);
                    if (k < 7) pw = mul2(pw, pstep);
                }
                float clo, chi; unpack2(corr2, clo, chi);
                y16_ptr[t*D_] = pack_hilo(yl[i] + clo + chi);
            }
        }
    } else {
        float q[N_];
        #pragma unroll
        for (int n = 0; n < N_; ++n)
            q[n] = g_hs[((b*NC + c)*N_ + n)*D_ + d];
        const float* dl_ptr = g_delta + (b*L_ + l0)*D_ + d;
        float a[N_];
        #pragma unroll
        for (int n = 0; n < N_; ++n)
            a[n] = -__expf(__ldg(A_log + d*N_ + n));
        for (int t = 0; t < CL; ++t) {
            const float dl = dl_ptr[t*D_];
            float corr = 0.f;
            #pragma unroll
            for (int n = 0; n < N_; ++n) {
                q[n] *= __expf(dl * a[n]);
                corr = fmaf(q[n], sC[t][n], corr);
            }
            y16_ptr[t*D_] = pack_hilo(y_ptr[t*D_] + corr);
        }
    }
}

// ---------------------------------------------------------------------------
// Kernel 5: out = y @ W_out^T via mma.sync bf16 split, prepacked (unchanged).
// ---------------------------------------------------------------------------
#define GP 72   // smem pitch in bf16 elements

__device__ __forceinline__ void mma_bf16(float dd[4],
                                         const uint32_t a[4],
                                         const uint32_t b[2]) {
    asm volatile(
        "mma.sync.aligned.m16n8k16.row.col.f32.bf16.bf16.f32 "
        "{%0,%1,%2,%3}, {%4,%5,%6,%7}, {%8,%9}, {%0,%1,%2,%3};"
        : "+f"(dd[0]), "+f"(dd[1]), "+f"(dd[2]), "+f"(dd[3])
        : "r"(a[0]), "r"(a[1]), "r"(a[2]), "r"(a[3]), "r"(b[0]), "r"(b[1]));
}

__global__ __launch_bounds__(256) void gemm_mma_kernel(float* __restrict__ out)
{
    extern __shared__ __nv_bfloat16 sm[];
    __nv_bfloat16* sA_hi = sm;                 // [128][GP]
    __nv_bfloat16* sA_lo = sm + 128*GP;
    __nv_bfloat16* sB_hi = sm + 2*128*GP;
    __nv_bfloat16* sB_lo = sm + 3*128*GP;

    const int tid  = threadIdx.x;
    const int wid  = tid >> 5;
    const int lane = tid & 31;
    const int gid  = lane >> 2;
    const int t4   = lane & 3;

    const int j0 = blockIdx.x * 128;
    const int m0 = blockIdx.y * 128;
    const int wm = (wid >> 2) * 64;
    const int wn = (wid & 3) * 32;

    float acc[4][4][4];
    #pragma unroll
    for (int i = 0; i < 4; ++i)
        #pragma unroll
        for (int j = 0; j < 4; ++j)
            #pragma unroll
            for (int q = 0; q < 4; ++q) acc[i][j][q] = 0.f;

    const int lrow = tid >> 5;
    const int lpc  = tid & 31;

    for (int kc = 0; kc < 256; kc += 64) {
        __syncthreads();
        #pragma unroll
        for (int rr = 0; rr < 16; ++rr) {
            const int row = lrow + rr*8;
            const int soff = row*GP + lpc*2;

            const uint2 wa = *reinterpret_cast<const uint2*>(
                g_y16 + (m0 + row)*D_ + kc + lpc*2);
            *reinterpret_cast<uint32_t*>(sA_hi + soff) = __byte_perm(wa.x, wa.y, 0x5410);
            *reinterpret_cast<uint32_t*>(sA_lo + soff) = __byte_perm(wa.x, wa.y, 0x7632);

            const uint2 wb = *reinterpret_cast<const uint2*>(
                g_W16 + (j0 + row)*D_ + kc + lpc*2);
            *reinterpret_cast<uint32_t*>(sB_hi + soff) = __byte_perm(wb.x, wb.y, 0x5410);
            *reinterpret_cast<uint32_t*>(sB_lo + soff) = __byte_perm(wb.x, wb.y, 0x7632);
        }
        __syncthreads();

        #pragma unroll
        for (int ks = 0; ks < 4; ++ks) {
            const int k0 = ks*16;
            uint32_t a_hi[4][4], a_lo[4][4], b_hi[4][2], b_lo[4][2];

            #pragma unroll
            for (int mf = 0; mf < 4; ++mf) {
                const int r0 = wm + mf*16 + gid;
                const int c0 = k0 + t4*2;
                a_hi[mf][0] = *reinterpret_cast<const uint32_t*>(sA_hi + (r0    )*GP + c0    );
                a_hi[mf][1] = *reinterpret_cast<const uint32_t*>(sA_hi + (r0 + 8)*GP + c0    );
                a_hi[mf][2] = *reinterpret_cast<const uint32_t*>(sA_hi + (r0    )*GP + c0 + 8);
                a_hi[mf][3] = *reinterpret_cast<const uint32_t*>(sA_hi + (r0 + 8)*GP + c0 + 8);
                a_lo[mf][0] = *reinterpret_cast<const uint32_t*>(sA_lo + (r0    )*GP + c0    );
                a_lo[mf][1] = *reinterpret_cast<const uint32_t*>(sA_lo + (r0 + 8)*GP + c0    );
                a_lo[mf][2] = *reinterpret_cast<const uint32_t*>(sA_lo + (r0    )*GP + c0 + 8);
                a_lo[mf][3] = *reinterpret_cast<const uint32_t*>(sA_lo + (r0 + 8)*GP + c0 + 8);
            }
            #pragma unroll
            for (int nf = 0; nf < 4; ++nf) {
                const int nr = wn + nf*8 + gid;
                const int c0 = k0 + t4*2;
                b_hi[nf][0] = *reinterpret_cast<const uint32_t*>(sB_hi + nr*GP + c0    );
                b_hi[nf][1] = *reinterpret_cast<const uint32_t*>(sB_hi + nr*GP + c0 + 8);
                b_lo[nf][0] = *reinterpret_cast<const uint32_t*>(sB_lo + nr*GP + c0    );
                b_lo[nf][1] = *reinterpret_cast<const uint32_t*>(sB_lo + nr*GP + c0 + 8);
            }

            #pragma unroll
            for (int mf = 0; mf < 4; ++mf)
                #pragma unroll
                for (int nf = 0; nf < 4; ++nf) {
                    mma_bf16(acc[mf][nf], a_hi[mf], b_hi[nf]);
                    mma_bf16(acc[mf][nf], a_hi[mf], b_lo[nf]);
                    mma_bf16(acc[mf][nf], a_lo[mf], b_hi[nf]);
                }
        }
    }

    #pragma unroll
    for (int mf = 0; mf < 4; ++mf) {
        const int mrow = m0 + wm + mf*16 + gid;
        #pragma unroll
        for (int nf = 0; nf < 4; ++nf) {
            const int ncol = j0 + wn + nf*8 + t4*2;
            *reinterpret_cast<float2*>(out + (size_t)mrow*D_ + ncol) =
                make_float2(acc[mf][nf][0], acc[mf][nf][1]);
            *reinterpret_cast<float2*>(out + (size_t)(mrow + 8)*D_ + ncol) =
                make_float2(acc[mf][nf][2], acc[mf][nf][3]);
        }
    }
}

// ---------------------------------------------------------------------------
extern "C" void kernel_launch(void* const* d_in, const int* in_sizes, int n_in,
                              void* d_out, int out_size)
{
    const float* x     = (const float*)d_in[0];
    const float* Wxp   = (const float*)d_in[1];
    const float* Wxb   = (const float*)d_in[2];
    const float* Wdt   = (const float*)d_in[3];
    const float* bdt   = (const float*)d_in[4];
    const float* A_log = (const float*)d_in[5];
    const float* Dskip = (const float*)d_in[6];
    const float* Wout  = (const float*)d_in[7];
    float* out = (float*)d_out;

    const int GEMM_SMEM = 4 * 128 * GP * (int)sizeof(__nv_bfloat16);  // 73728 B
    cudaFuncSetAttribute(gemm_mma_kernel,
                         cudaFuncAttributeMaxDynamicSharedMemorySize, GEMM_SMEM);

    packW_kernel     <<<(D_*D_)/256, 256>>>(Wout);
    proj_kernel      <<<(B_*L_)/16, 256>>>(x, Wxp, Wxb, Wdt, bdt);
    scan_local_kernel<<<B_*NC,      256>>>(x, A_log, Dskip);
    combine_kernel   <<<B_*N_,      512>>>();
    correct2_kernel  <<<B_*NC,      256>>>(A_log);
    gemm_mma_kernel  <<<dim3(2, 128), 256, GEMM_SMEM>>>(out);
}

// round 11
// speedup vs baseline: 1.0094x; 1.0094x over previous
#include <cuda_runtime.h>
#include <cuda_bf16.h>
#include <math.h>
#include <stdint.h>

#define B_    8
#define L_    2048
#define D_    256
#define N_    16
#define R_    16
#define CL    32          // scan chunk length
#define NC    (L_/CL)     // 64 chunks
#define SEGC  (NC/4)      // 16 chunks per combine segment

typedef unsigned long long ull;

// ---------------- scratch (device globals) ----------------
__device__ float    g_delta  [B_*L_*D_];      // slow-path only
__device__ float    g_C      [B_*L_*16];      // C projections (for correct2)
__device__ float    g_pc     [B_*L_*D_];      // cumulative p1 within chunk
__device__ float    g_P      [B_*NC*N_*D_];
__device__ float    g_H      [B_*NC*N_*D_];
__device__ float    g_hs     [B_*NC*N_*D_];
__device__ float    g_y      [B_*L_*D_];      // y_local (pre-correction)
__device__ uint32_t g_y16    [B_*L_*D_];      // final y packed (bf16 hi | lo<<16)
__device__ uint32_t g_W16    [D_*D_];         // W_out packed (bf16 hi | lo<<16)

__device__ __forceinline__ float softplusf(float v) {
    return v > 20.0f ? v : log1pf(__expf(v));
}

__device__ __forceinline__ uint32_t pack_hilo(float v) {
    __nv_bfloat16 h = __float2bfloat16(v);
    __nv_bfloat16 l = __float2bfloat16(v - __bfloat162float(h));
    return (uint32_t)__bfloat16_as_ushort(h) |
           ((uint32_t)__bfloat16_as_ushort(l) << 16);
}

// ---------------- packed f32x2 helpers ----------------
__device__ __forceinline__ ull pack2(float lo, float hi) {
    ull r;
    asm("mov.b64 %0, {%1, %2};" : "=l"(r) : "f"(lo), "f"(hi));
    return r;
}
__device__ __forceinline__ void unpack2(ull v, float& lo, float& hi) {
    asm("mov.b64 {%0, %1}, %2;" : "=f"(lo), "=f"(hi) : "l"(v));
}
__device__ __forceinline__ ull mul2(ull a, ull b) {
    ull d;
    asm("mul.rn.f32x2 %0, %1, %2;" : "=l"(d) : "l"(a), "l"(b));
    return d;
}
__device__ __forceinline__ ull fma2(ull a, ull b, ull c) {
    ull d;
    asm("fma.rn.f32x2 %0, %1, %2, %3;" : "=l"(d) : "l"(a), "l"(b), "l"(c));
    return d;
}
__device__ __forceinline__ void powers16_p2(float p1, ull e2[8]) {
    const float p1sq = p1 * p1;
    e2[0] = pack2(p1, p1sq);
    const ull pstep = pack2(p1sq, p1sq);
    #pragma unroll
    for (int k = 1; k < 8; ++k) e2[k] = mul2(e2[k-1], pstep);
}

__device__ __forceinline__ float check_A(const float* __restrict__ A_log,
                                         int d, bool& fast) {
    float a0 = -__expf(__ldg(A_log + d*N_));
    fast = true;
    #pragma unroll
    for (int n = 1; n < N_; ++n) {
        float an = -__expf(__ldg(A_log + d*N_ + n));
        fast = fast && (fabsf(an - a0*(float)(n+1)) <= 1e-4f*(float)(n+1));
    }
    return a0;
}

// ---------------------------------------------------------------------------
// Kernel 0: pack W_out to bf16 hi/lo once.
// ---------------------------------------------------------------------------
__global__ __launch_bounds__(256) void packW_kernel(const float* __restrict__ Wout)
{
    const int i = blockIdx.x*256 + threadIdx.x;
    g_W16[i] = pack_hilo(Wout[i]);
}

// ---------------------------------------------------------------------------
// Kernel 1 (FUSED): projections + local scan for a mirror chunk pair.
// Block = (b, pair c / c'=NC-1-c). 64 rows: [0:32)=chunk c, [32:64)=chunk c'.
// smem: sx[64][256] fp32 x rows; sp[64][80] projections.
//   sp cols: [0:16)=delta_r, [16:32)=Bf, [32:48)=Bb, [48:64)=C, [64:80)=xb-proj.
// Scan chunk c step t: x-proj row t, mirror row 63-t (xb-proj + xr).
// Scan chunk c' step t: x-proj row 32+t, mirror row 31-t.
// ---------------------------------------------------------------------------
__global__ __launch_bounds__(256, 2) void fps_kernel(
    const float* __restrict__ x, const float* __restrict__ Wxp,
    const float* __restrict__ Wxb, const float* __restrict__ Wdt,
    const float* __restrict__ bdt, const float* __restrict__ A_log,
    const float* __restrict__ Dskip)
{
    extern __shared__ __align__(16) float fsm[];
    float* sx = fsm;                // [64][256]  64 KB
    float* sp = fsm + 64*256;       // [64][80]   20 KB

    const int bp = blockIdx.x;      // 0 .. B_*NC/2-1
    const int b  = bp >> 5;         // NC/2 = 32 pairs
    const int c  = bp & 31;
    const int cp = NC - 1 - c;
    const int tid = threadIdx.x;

    // Phase 1: load 64 x rows (chunk c then chunk c')
    for (int i = tid; i < 64*256; i += 256) {
        const int r = i >> 8, col = i & 255;
        const int l = (r < 32) ? c*CL + r : cp*CL + (r - 32);
        sx[i] = x[(b*L_ + l)*D_ + col];
    }
    __syncthreads();

    // Phase 2: stage A — 80 projections x 64 rows (8 warps x 10 outputs)
    {
        const int warp = tid >> 5, lane = tid & 31;
        #pragma unroll
        for (int t = 0; t < 10; ++t) {
            const int j = warp + 8*t;
            const float* Wrow = (j < 64) ? (Wxp + j*D_) : (Wxb + (j-64)*D_);
            float wv[8];
            #pragma unroll
            for (int k = 0; k < 8; ++k) wv[k] = __ldg(Wrow + lane + 32*k);
            for (int r = 0; r < 64; ++r) {
                float acc = 0.f;
                #pragma unroll
                for (int k = 0; k < 8; ++k)
                    acc = fmaf(wv[k], sx[r*256 + lane + 32*k], acc);
                #pragma unroll
                for (int o = 16; o; o >>= 1)
                    acc += __shfl_xor_sync(0xffffffffu, acc, o);
                if (lane == 0) sp[r*80 + j] = acc;
            }
        }
    }
    __syncthreads();

    // Phase 3: write C projections for correct2
    for (int i = tid; i < 64*16; i += 256) {
        const int r = i >> 4, jj = i & 15;
        const int l = (r < 32) ? c*CL + r : cp*CL + (r - 32);
        g_C[(b*L_ + l)*16 + jj] = sp[r*80 + 48 + jj];
    }

    // Phase 4: per-channel scan over both chunks
    const int d = tid;
    float wdt[R_];
    #pragma unroll
    for (int q = 0; q < R_; ++q) wdt[q] = __ldg(Wdt + d*R_ + q);
    const float bv  = bdt[d];
    const float dsk = Dskip[d];
    bool fast;
    const float a0 = check_A(A_log, d, fast);

    #pragma unroll 1
    for (int sel = 0; sel < 2; ++sel) {
        const int rb = sel * 32;
        const int cc = sel ? cp : c;
        const int l0 = cc * CL;

        float* y_ptr  = g_y  + (b*L_ + l0)*D_ + d;
        float* pc_ptr = g_pc + (b*L_ + l0)*D_ + d;
        float* Pp = g_P + ((b*NC + cc)*N_)*D_ + d;
        float* Hp = g_H + ((b*NC + cc)*N_)*D_ + d;

        if (fast) {
            ull h2[8];
            #pragma unroll
            for (int k = 0; k < 8; ++k) h2[k] = 0ull;
            float p1 = 1.f;

            #pragma unroll 4
            for (int t = 0; t < CL; ++t) {
                const int rowA = rb + t;
                const int rowB = sel ? (31 - t) : (63 - t);

                // dt dots (two partial sums each for ILP)
                const float2* qa = reinterpret_cast<const float2*>(&sp[rowA*80]);
                const float2* qb = reinterpret_cast<const float2*>(&sp[rowB*80 + 64]);
                float s0 = bv, s1 = 0.f, sb0 = bv, sb1 = 0.f;
                #pragma unroll
                for (int q = 0; q < 8; ++q) {
                    const float2 av = qa[q], bvv = qb[q];
                    s0  = fmaf(av.x,  wdt[2*q],   s0);
                    s1  = fmaf(av.y,  wdt[2*q+1], s1);
                    sb0 = fmaf(bvv.x, wdt[2*q],   sb0);
                    sb1 = fmaf(bvv.y, wdt[2*q+1], sb1);
                }
                const float dl  = softplusf(s0 + s1);
                const float dlb = softplusf(sb0 + sb1);

                const float xv = sx[rowA*256 + d];
                const float xr = sx[rowB*256 + d];

                const float e1 = __expf(dl * a0);
                const float e1sq = e1 * e1;
                ull e = pack2(e1, e1sq);
                const ull estep = pack2(e1sq, e1sq);
                const float c1 = dl * xv, c2 = dlb * xr;
                const ull c1p = pack2(c1, c1);
                const ull c2p = pack2(c2, c2);
                ull y2 = 0ull;
                const ull* Bf2 = reinterpret_cast<const ull*>(&sp[rowA*80 + 16]);
                const ull* Bb2 = reinterpret_cast<const ull*>(&sp[rowA*80 + 32]);
                const ull* C2  = reinterpret_cast<const ull*>(&sp[rowA*80 + 48]);
                #pragma unroll
                for (int k = 0; k < 8; ++k) {
                    const ull du = fma2(c1p, Bf2[k], mul2(c2p, Bb2[k]));
                    h2[k] = fma2(e, h2[k], du);
                    y2    = fma2(h2[k], C2[k], y2);
                    if (k < 7) e = mul2(e, estep);
                }
                p1 *= e1;
                float ylo, yhi; unpack2(y2, ylo, yhi);
                y_ptr [t*D_] = fmaf(xv + xr, dsk, ylo + yhi);
                pc_ptr[t*D_] = p1;
            }
            ull pw2[8]; powers16_p2(p1, pw2);
            #pragma unroll
            for (int k = 0; k < 8; ++k) {
                float plo, phi; unpack2(pw2[k], plo, phi);
                float hlo, hhi; unpack2(h2[k], hlo, hhi);
                Pp[(2*k  )*D_] = plo;  Pp[(2*k+1)*D_] = phi;
                Hp[(2*k  )*D_] = hlo;  Hp[(2*k+1)*D_] = hhi;
            }
        } else {
            float h[N_], a[N_], p[N_];
            #pragma unroll
            for (int n = 0; n < N_; ++n) {
                a[n] = -__expf(__ldg(A_log + d*N_ + n));
                p[n] = 1.f;
                h[n] = 0.f;
            }
            for (int t = 0; t < CL; ++t) {
                const int rowA = rb + t;
                const int rowB = sel ? (31 - t) : (63 - t);
                float s = bv, sb = bv;
                #pragma unroll
                for (int q = 0; q < R_; ++q) {
                    s  = fmaf(sp[rowA*80 + q],      wdt[q], s);
                    sb = fmaf(sp[rowB*80 + 64 + q], wdt[q], sb);
                }
                const float dl  = softplusf(s);
                const float dlb = softplusf(sb);
                g_delta[(b*L_ + l0 + t)*D_ + d] = dl;   // for correct2 slow path
                const float xv = sx[rowA*256 + d];
                const float xr = sx[rowB*256 + d];
                const float c1 = dl*xv, c2 = dlb*xr;
                float y = 0.f;
                #pragma unroll
                for (int n = 0; n < N_; ++n) {
                    const float e = __expf(dl * a[n]);
                    h[n] = fmaf(e, h[n], fmaf(c1, sp[rowA*80 + 16 + n],
                                              c2 * sp[rowA*80 + 32 + n]));
                    y    = fmaf(h[n], sp[rowA*80 + 48 + n], y);
                    p[n] *= e;
                }
                y_ptr[t*D_] = fmaf(xv + xr, dsk, y);
            }
            #pragma unroll
            for (int n = 0; n < N_; ++n) { Pp[n*D_] = p[n]; Hp[n*D_] = h[n]; }
        }
    }
}

// ---------------------------------------------------------------------------
// Kernel 2: combine — segmented affine scan (unchanged).
// ---------------------------------------------------------------------------
__global__ __launch_bounds__(512) void combine_kernel()
{
    const int bn = blockIdx.x;          // 0..127
    const int b = bn >> 4;
    const int n = bn & 15;
    const int seg = threadIdx.x >> 7;   // 0..3
    const int dp  = threadIdx.x & 127;  // d-pair

    __shared__ ull sP[4][128];
    __shared__ ull sH[4][128];

    const ull* P2 = reinterpret_cast<const ull*>(g_P);
    const ull* H2 = reinterpret_cast<const ull*>(g_H);
    ull* hs2 = reinterpret_cast<ull*>(g_hs);

    const int c0 = seg * SEGC;
    #define CIDX(c) ((((b*NC + (c))*N_) + n)*128 + dp)

    ull Pc = pack2(1.f, 1.f), Hc = 0ull;
    #pragma unroll 4
    for (int i = 0; i < SEGC; ++i) {
        const int idx = CIDX(c0 + i);
        const ull p = P2[idx];
        Pc = mul2(p, Pc);
        Hc = fma2(p, Hc, H2[idx]);
    }
    sP[seg][dp] = Pc;
    sH[seg][dp] = Hc;
    __syncthreads();

    ull h = 0ull;
    #pragma unroll
    for (int t = 0; t < 3; ++t)
        if (t < seg) h = fma2(sP[t][dp], h, sH[t][dp]);

    #pragma unroll 4
    for (int i = 0; i < SEGC; ++i) {
        const int idx = CIDX(c0 + i);
        hs2[idx] = h;
        h = fma2(P2[idx], h, H2[idx]);
    }
    #undef CIDX
}

// ---------------------------------------------------------------------------
// Kernel 3: correct2 — y += pcum^n * hs * C; emits packed y16.
// ---------------------------------------------------------------------------
__global__ __launch_bounds__(256) void correct2_kernel(
    const float* __restrict__ A_log)
{
    const int bc = blockIdx.x;
    const int b = bc / NC, c = bc - b*NC;
    const int d = threadIdx.x;
    const int l0 = c * CL;

    __shared__ __align__(16) float sC[CL][N_];
    for (int i = d; i < CL*N_; i += 256) {
        int t = i >> 4, j = i & 15;
        sC[t][j] = g_C[(b*L_ + l0 + t)*16 + j];
    }
    __syncthreads();

    bool fast;
    const float a0 = check_A(A_log, d, fast);
    (void)a0;

    const float* y_ptr  = g_y  + (b*L_ + l0)*D_ + d;
    uint32_t* y16_ptr   = g_y16 + (b*L_ + l0)*D_ + d;
    const float* pc_ptr = g_pc + (b*L_ + l0)*D_ + d;

    if (fast) {
        ull q2[8];
        #pragma unroll
        for (int k = 0; k < 8; ++k) {
            const float qlo = g_hs[((b*NC + c)*N_ + 2*k  )*D_ + d];
            const float qhi = g_hs[((b*NC + c)*N_ + 2*k+1)*D_ + d];
            q2[k] = pack2(qlo, qhi);
        }
        #pragma unroll
        for (int t0 = 0; t0 < CL; t0 += 4) {
            float p1[4], yl[4];
            #pragma unroll
            for (int i = 0; i < 4; ++i) {
                p1[i] = pc_ptr[(t0+i)*D_];
                yl[i] = y_ptr [(t0+i)*D_];
            }
            #pragma unroll
            for (int i = 0; i < 4; ++i) {
                const int t = t0 + i;
                const float psq = p1[i] * p1[i];
                ull pw = pack2(p1[i], psq);
                const ull pstep = pack2(psq, psq);
                const ull* C2 = reinterpret_cast<const ull*>(&sC[t][0]);
                ull corr2 = 0ull;
                #pragma unroll
                for (int k = 0; k < 8; ++k) {
                    corr2 = fma2(mul2(pw, q2[k]), C2[k], corr2);
                    if (k < 7) pw = mul2(pw, pstep);
                }
                float clo, chi; unpack2(corr2, clo, chi);
                y16_ptr[t*D_] = pack_hilo(yl[i] + clo + chi);
            }
        }
    } else {
        float q[N_];
        #pragma unroll
        for (int n = 0; n < N_; ++n)
            q[n] = g_hs[((b*NC + c)*N_ + n)*D_ + d];
        const float* dl_ptr = g_delta + (b*L_ + l0)*D_ + d;
        float a[N_];
        #pragma unroll
        for (int n = 0; n < N_; ++n)
            a[n] = -__expf(__ldg(A_log + d*N_ + n));
        for (int t = 0; t < CL; ++t) {
            const float dl = dl_ptr[t*D_];
            float corr = 0.f;
            #pragma unroll
            for (int n = 0; n < N_; ++n) {
                q[n] *= __expf(dl * a[n]);
                corr = fmaf(q[n], sC[t][n], corr);
            }
            y16_ptr[t*D_] = pack_hilo(y_ptr[t*D_] + corr);
        }
    }
}

// ---------------------------------------------------------------------------
// Kernel 4: out = y @ W_out^T via mma.sync bf16 split, prepacked (unchanged).
// ---------------------------------------------------------------------------
#define GP 72   // smem pitch in bf16 elements

__device__ __forceinline__ void mma_bf16(float dd[4],
                                         const uint32_t a[4],
                                         const uint32_t b[2]) {
    asm volatile(
        "mma.sync.aligned.m16n8k16.row.col.f32.bf16.bf16.f32 "
        "{%0,%1,%2,%3}, {%4,%5,%6,%7}, {%8,%9}, {%0,%1,%2,%3};"
        : "+f"(dd[0]), "+f"(dd[1]), "+f"(dd[2]), "+f"(dd[3])
        : "r"(a[0]), "r"(a[1]), "r"(a[2]), "r"(a[3]), "r"(b[0]), "r"(b[1]));
}

__global__ __launch_bounds__(256) void gemm_mma_kernel(float* __restrict__ out)
{
    extern __shared__ __nv_bfloat16 sm[];
    __nv_bfloat16* sA_hi = sm;                 // [128][GP]
    __nv_bfloat16* sA_lo = sm + 128*GP;
    __nv_bfloat16* sB_hi = sm + 2*128*GP;
    __nv_bfloat16* sB_lo = sm + 3*128*GP;

    const int tid  = threadIdx.x;
    const int wid  = tid >> 5;
    const int lane = tid & 31;
    const int gid  = lane >> 2;
    const int t4   = lane & 3;

    const int j0 = blockIdx.x * 128;
    const int m0 = blockIdx.y * 128;
    const int wm = (wid >> 2) * 64;
    const int wn = (wid & 3) * 32;

    float acc[4][4][4];
    #pragma unroll
    for (int i = 0; i < 4; ++i)
        #pragma unroll
        for (int j = 0; j < 4; ++j)
            #pragma unroll
            for (int q = 0; q < 4; ++q) acc[i][j][q] = 0.f;

    const int lrow = tid >> 5;
    const int lpc  = tid & 31;

    for (int kc = 0; kc < 256; kc += 64) {
        __syncthreads();
        #pragma unroll
        for (int rr = 0; rr < 16; ++rr) {
            const int row = lrow + rr*8;
            const int soff = row*GP + lpc*2;

            const uint2 wa = *reinterpret_cast<const uint2*>(
                g_y16 + (m0 + row)*D_ + kc + lpc*2);
            *reinterpret_cast<uint32_t*>(sA_hi + soff) = __byte_perm(wa.x, wa.y, 0x5410);
            *reinterpret_cast<uint32_t*>(sA_lo + soff) = __byte_perm(wa.x, wa.y, 0x7632);

            const uint2 wb = *reinterpret_cast<const uint2*>(
                g_W16 + (j0 + row)*D_ + kc + lpc*2);
            *reinterpret_cast<uint32_t*>(sB_hi + soff) = __byte_perm(wb.x, wb.y, 0x5410);
            *reinterpret_cast<uint32_t*>(sB_lo + soff) = __byte_perm(wb.x, wb.y, 0x7632);
        }
        __syncthreads();

        #pragma unroll
        for (int ks = 0; ks < 4; ++ks) {
            const int k0 = ks*16;
            uint32_t a_hi[4][4], a_lo[4][4], b_hi[4][2], b_lo[4][2];

            #pragma unroll
            for (int mf = 0; mf < 4; ++mf) {
                const int r0 = wm + mf*16 + gid;
                const int c0 = k0 + t4*2;
                a_hi[mf][0] = *reinterpret_cast<const uint32_t*>(sA_hi + (r0    )*GP + c0    );
                a_hi[mf][1] = *reinterpret_cast<const uint32_t*>(sA_hi + (r0 + 8)*GP + c0    );
                a_hi[mf][2] = *reinterpret_cast<const uint32_t*>(sA_hi + (r0    )*GP + c0 + 8);
                a_hi[mf][3] = *reinterpret_cast<const uint32_t*>(sA_hi + (r0 + 8)*GP + c0 + 8);
                a_lo[mf][0] = *reinterpret_cast<const uint32_t*>(sA_lo + (r0    )*GP + c0    );
                a_lo[mf][1] = *reinterpret_cast<const uint32_t*>(sA_lo + (r0 + 8)*GP + c0    );
                a_lo[mf][2] = *reinterpret_cast<const uint32_t*>(sA_lo + (r0    )*GP + c0 + 8);
                a_lo[mf][3] = *reinterpret_cast<const uint32_t*>(sA_lo + (r0 + 8)*GP + c0 + 8);
            }
            #pragma unroll
            for (int nf = 0; nf < 4; ++nf) {
                const int nr = wn + nf*8 + gid;
                const int c0 = k0 + t4*2;
                b_hi[nf][0] = *reinterpret_cast<const uint32_t*>(sB_hi + nr*GP + c0    );
                b_hi[nf][1] = *reinterpret_cast<const uint32_t*>(sB_hi + nr*GP + c0 + 8);
                b_lo[nf][0] = *reinterpret_cast<const uint32_t*>(sB_lo + nr*GP + c0    );
                b_lo[nf][1] = *reinterpret_cast<const uint32_t*>(sB_lo + nr*GP + c0 + 8);
            }

            #pragma unroll
            for (int mf = 0; mf < 4; ++mf)
                #pragma unroll
                for (int nf = 0; nf < 4; ++nf) {
                    mma_bf16(acc[mf][nf], a_hi[mf], b_hi[nf]);
                    mma_bf16(acc[mf][nf], a_hi[mf], b_lo[nf]);
                    mma_bf16(acc[mf][nf], a_lo[mf], b_hi[nf]);
                }
        }
    }

    #pragma unroll
    for (int mf = 0; mf < 4; ++mf) {
        const int mrow = m0 + wm + mf*16 + gid;
        #pragma unroll
        for (int nf = 0; nf < 4; ++nf) {
            const int ncol = j0 + wn + nf*8 + t4*2;
            *reinterpret_cast<float2*>(out + (size_t)mrow*D_ + ncol) =
                make_float2(acc[mf][nf][0], acc[mf][nf][1]);
            *reinterpret_cast<float2*>(out + (size_t)(mrow + 8)*D_ + ncol) =
                make_float2(acc[mf][nf][2], acc[mf][nf][3]);
        }
    }
}

// ---------------------------------------------------------------------------
extern "C" void kernel_launch(void* const* d_in, const int* in_sizes, int n_in,
                              void* d_out, int out_size)
{
    const float* x     = (const float*)d_in[0];
    const float* Wxp   = (const float*)d_in[1];
    const float* Wxb   = (const float*)d_in[2];
    const float* Wdt   = (const float*)d_in[3];
    const float* bdt   = (const float*)d_in[4];
    const float* A_log = (const float*)d_in[5];
    const float* Dskip = (const float*)d_in[6];
    const float* Wout  = (const float*)d_in[7];
    float* out = (float*)d_out;

    const int GEMM_SMEM = 4 * 128 * GP * (int)sizeof(__nv_bfloat16);  // 73728 B
    const int FPS_SMEM  = (64*256 + 64*80) * (int)sizeof(float);      // 86016 B
    cudaFuncSetAttribute(gemm_mma_kernel,
                         cudaFuncAttributeMaxDynamicSharedMemorySize, GEMM_SMEM);
    cudaFuncSetAttribute(fps_kernel,
                         cudaFuncAttributeMaxDynamicSharedMemorySize, FPS_SMEM);

    packW_kernel   <<<(D_*D_)/256, 256>>>(Wout);
    fps_kernel     <<<B_*(NC/2), 256, FPS_SMEM>>>(x, Wxp, Wxb, Wdt, bdt,
                                                  A_log, Dskip);
    combine_kernel <<<B_*N_, 512>>>();
    correct2_kernel<<<B_*NC, 256>>>(A_log);
    gemm_mma_kernel<<<dim3(2, 128), 256, GEMM_SMEM>>>(out);
}